// round 4
// baseline (speedup 1.0000x reference)
#include <cuda_runtime.h>
#include <cstdint>

// Problem constants
#define NMB 32          // N*M
#define TLEN 300
#define VJ 25
#define CH 64
#define KT 9
#define NSKEL (NMB*TLEN)          // 9600 skeletons

// -------- scratch --------
__device__ float g_xg[NMB*VJ*TLEN*CH];   // GCN output (nm, v, t, c), tf32-rounded
__device__ float g_wtf[KT*CH*CH];        // conv weight [k][ci][co], tf32-rounded
__device__ float g_scale[CH];            // BN fold: gamma/sqrt(var+eps)
__device__ float g_shift[CH];            // (conv_b - mean)*scale + beta

__device__ __forceinline__ float to_tf32(float v) {
    uint32_t u;
    asm("cvt.rna.tf32.f32 %0, %1;" : "=r"(u) : "f"(v));
    return __uint_as_float(u);
}

__device__ __forceinline__ void cp_async16(void* dst_smem, const void* src) {
    uint32_t d = (uint32_t)__cvta_generic_to_shared(dst_smem);
    asm volatile("cp.async.ca.shared.global [%0], [%1], 16;" :: "r"(d), "l"(src));
}
#define CP_COMMIT() asm volatile("cp.async.commit_group;")
#define CP_WAIT0()  asm volatile("cp.async.wait_group 0;")

__device__ __forceinline__ void mma_tf32(float* d, const uint32_t* a, uint32_t b0, uint32_t b1) {
    asm volatile("mma.sync.aligned.m16n8k8.row.col.f32.tf32.tf32.f32 "
        "{%0,%1,%2,%3}, {%4,%5,%6,%7}, {%8,%9}, {%0,%1,%2,%3};"
        : "+f"(d[0]), "+f"(d[1]), "+f"(d[2]), "+f"(d[3])
        : "r"(a[0]), "r"(a[1]), "r"(a[2]), "r"(a[3]), "r"(b0), "r"(b1));
}

// ============================ prep ============================
__global__ void prep_kernel(const float* __restrict__ conv_w,
                            const float* __restrict__ conv_b,
                            const float* __restrict__ bn_gamma,
                            const float* __restrict__ bn_beta,
                            const float* __restrict__ bn_mean,
                            const float* __restrict__ bn_var) {
    const int gtid = blockIdx.x * blockDim.x + threadIdx.x;
    const int gstride = gridDim.x * blockDim.x;
    if (gtid < CH) {
        float inv = bn_gamma[gtid] * rsqrtf(bn_var[gtid] + 1e-5f);
        g_scale[gtid] = inv;
        g_shift[gtid] = (conv_b[gtid] - bn_mean[gtid]) * inv + bn_beta[gtid];
    }
    // conv_w (co, ci, k, 1) -> g_wtf[k][ci][co], tf32
    for (int i = gtid; i < CH*CH*KT; i += gstride) {
        int k   = i / (CH*CH);
        int rem = i - k*(CH*CH);
        int ci  = rem >> 6;
        int co  = rem & 63;
        g_wtf[i] = to_tf32(conv_w[(co*CH + ci)*KT + k]);
    }
}

// ============================ GCN (full MMA) ============================
// Block = 4 skeletons (100 rows, padded 112). 256 threads = 8 warps.
// GEMM1: hw = hs(112x64) @ Ws(64x64), warps 0-6 one m16 tile each.
// GEMM2: x = Ah(32x32 padded) @ hw_s(32x64) per skeleton, 8 warp-tiles.
#define GSTR_H 68
#define GSTR_W 72
#define GSTR_HW 72
#define GSTR_A 36
#define GCN_S 4

__global__ __launch_bounds__(256, 2)
void gcn_kernel(const float* __restrict__ h,
                const float* __restrict__ adj,
                const float* __restrict__ gcn_w,
                const float* __restrict__ gcn_b) {
    extern __shared__ float sm[];
    float* hs  = sm;                       // 112*68
    float* Ws  = hs  + 112*GSTR_H;         // 64*72
    float* hw  = Ws  + 64*GSTR_W;          // 128*72 (4 skel x 32 rows)
    float* Ah  = hw  + 128*GSTR_HW;        // 32*36
    float* gb  = Ah  + 32*GSTR_A;          // 64
    float* nrm = gb  + CH;                 // 25

    const int tid = threadIdx.x;
    const int g0  = blockIdx.x * GCN_S;
    const float* hbase = h + (long long)g0 * VJ * CH;

    // norm[v] = rsqrt(deg)
    if (tid < VJ) {
        float s = 0.f;
        for (int u = 0; u < VJ; u++) s += adj[tid*VJ + u];
        nrm[tid] = rsqrtf(s);
    }
    // hs: 112 rows, tf32 (rows >=100 zero)
    for (int i = tid; i < 112*16; i += 256) {
        int r = i >> 4, c4 = (i & 15) * 4;
        float4 v = make_float4(0,0,0,0);
        if (r < 100) {
            v = *(const float4*)&hbase[r*CH + c4];
            v.x = to_tf32(v.x); v.y = to_tf32(v.y); v.z = to_tf32(v.z); v.w = to_tf32(v.w);
        }
        *(float4*)&hs[r*GSTR_H + c4] = v;
    }
    // Ws: gcn_w[ci][co], tf32
    for (int i = tid; i < CH*16; i += 256) {
        int r = i >> 4, c4 = (i & 15) * 4;
        float4 v = *(const float4*)&gcn_w[r*CH + c4];
        v.x = to_tf32(v.x); v.y = to_tf32(v.y); v.z = to_tf32(v.z); v.w = to_tf32(v.w);
        *(float4*)&Ws[r*GSTR_W + c4] = v;
    }
    // zero hw pad rows (v = 25..31 of each skeleton), full stride width
    for (int i = tid; i < GCN_S*7*18; i += 256) {
        int j = i / 18, c4 = (i % 18) * 4;
        int s = j / 7, rr = j % 7;
        *(float4*)&hw[(s*32 + 25 + rr)*GSTR_HW + c4] = make_float4(0,0,0,0);
    }
    if (tid < CH) gb[tid] = gcn_b[tid];
    __syncthreads();

    // Ah: tf32(norm[v]*adj[v][u]*norm[u]), zero-padded to 32x32
    for (int i = tid; i < 32*32; i += 256) {
        int v = i >> 5, u = i & 31;
        Ah[v*GSTR_A + u] = (v < VJ && u < VJ) ? to_tf32(nrm[v]*adj[v*VJ+u]*nrm[u]) : 0.f;
    }
    __syncthreads();

    const int lane = tid & 31, w = tid >> 5;
    const int gID = lane >> 2, tig = lane & 3;

    // ---- GEMM1: warps 0-6, m16 tile at rows w*16 ----
    if (w < 7) {
        float acc[8][4];
#pragma unroll
        for (int nb = 0; nb < 8; nb++)
#pragma unroll
            for (int j = 0; j < 4; j++) acc[nb][j] = 0.f;
#pragma unroll
        for (int kk = 0; kk < 8; kk++) {
            const float* xp = hs + (w*16 + gID)*GSTR_H + kk*8 + tig;
            uint32_t a[4];
            a[0] = __float_as_uint(xp[0]);
            a[1] = __float_as_uint(xp[8*GSTR_H]);
            a[2] = __float_as_uint(xp[4]);
            a[3] = __float_as_uint(xp[8*GSTR_H + 4]);
            const float* wp = Ws + (kk*8 + tig)*GSTR_W + gID;
#pragma unroll
            for (int nb = 0; nb < 8; nb++) {
                uint32_t b0 = __float_as_uint(wp[nb*8]);
                uint32_t b1 = __float_as_uint(wp[nb*8 + 4*GSTR_W]);
                mma_tf32(acc[nb], a, b0, b1);
            }
        }
        // store tf32 to hw with 32-rows-per-skeleton remap
#pragma unroll
        for (int nb = 0; nb < 8; nb++) {
            int c = nb*8 + tig*2;
#pragma unroll
            for (int rr = 0; rr < 2; rr++) {
                int r = w*16 + gID + rr*8;
                if (r < 100) {
                    int s = r / VJ, vv = r - s*VJ;
                    float2 val = make_float2(to_tf32(acc[nb][rr*2]), to_tf32(acc[nb][rr*2+1]));
                    *(float2*)&hw[(s*32 + vv)*GSTR_HW + c] = val;
                }
            }
        }
    }
    __syncthreads();

    // ---- GEMM2: x = Ah @ hw_s. Warp w: skeleton s=w/2, m-tile mt=w&1 ----
    {
        const int s = w >> 1, mt = w & 1;
        float acc[8][4];
#pragma unroll
        for (int nb = 0; nb < 8; nb++)
#pragma unroll
            for (int j = 0; j < 4; j++) acc[nb][j] = 0.f;
#pragma unroll
        for (int kk = 0; kk < 4; kk++) {
            const float* ap = Ah + (mt*16 + gID)*GSTR_A + kk*8 + tig;
            uint32_t a[4];
            a[0] = __float_as_uint(ap[0]);
            a[1] = __float_as_uint(ap[8*GSTR_A]);
            a[2] = __float_as_uint(ap[4]);
            a[3] = __float_as_uint(ap[8*GSTR_A + 4]);
            const float* wp = hw + (s*32 + kk*8 + tig)*GSTR_HW + gID;
#pragma unroll
            for (int nb = 0; nb < 8; nb++) {
                uint32_t b0 = __float_as_uint(wp[nb*8]);
                uint32_t b1 = __float_as_uint(wp[nb*8 + 4*GSTR_HW]);
                mma_tf32(acc[nb], a, b0, b1);
            }
        }
        // epilogue: +bias, relu, tf32-round, store to g_xg
        const int g = g0 + s;
        const int nm = g / TLEN, t = g % TLEN;
#pragma unroll
        for (int nb = 0; nb < 8; nb++) {
            int c = nb*8 + tig*2;
            float2 gbv = *(const float2*)&gb[c];
#pragma unroll
            for (int rr = 0; rr < 2; rr++) {
                int vv = mt*16 + gID + rr*8;
                if (vv < VJ) {
                    float x0 = to_tf32(fmaxf(acc[nb][rr*2]   + gbv.x, 0.f));
                    float x1 = to_tf32(fmaxf(acc[nb][rr*2+1] + gbv.y, 0.f));
                    *(float2*)&g_xg[((nm*VJ + vv)*TLEN + t)*CH + c] = make_float2(x0, x1);
                }
            }
        }
    }
}

// ============================ Conv (MMA, m32 warp tiles, cp.async) ============================
// Block = half a (nm,v) slab (150 t-rows). 160 threads = 5 warps.
// Warp w: rows [w*32, w*32+32) x all 64 c_out. X smem stride 68, W double-buffered stride 72.
#define XSTR 68
#define WSTR 72
#define XROWS 168
#define CONV_THREADS 160

__global__ __launch_bounds__(CONV_THREADS, 2)
void conv_mma_kernel(const float* __restrict__ h, float* __restrict__ out) {
    extern __shared__ float sm[];
    float* xs = sm;                      // 168*68
    float* wb = sm + XROWS*XSTR;         // 2 * 64*72

    const int tid  = threadIdx.x;
    const int bid  = blockIdx.x;
    const int slab = bid >> 1;
    const int half = bid & 1;
    const int nm = slab / VJ, v = slab % VJ;
    const int tbase = half * 150;
    const float* xg = g_xg + (long long)slab * TLEN * CH;

    // X fill via cp.async (g_xg already tf32). smem row r <-> t = tbase-4+r.
    for (int i = tid; i < XROWS*16; i += CONV_THREADS) {
        int r = i >> 4, c4 = (i & 15) * 4;
        int tg = tbase - 4 + r;
        float* dst = &xs[r*XSTR + c4];
        if (r < 158 && tg >= 0 && tg < TLEN)
            cp_async16(dst, xg + tg*CH + c4);
        else
            *(float4*)dst = make_float4(0,0,0,0);
    }
    // W tap 0
    for (int i = tid; i < CH*16; i += CONV_THREADS) {
        int r = i >> 4, c4 = (i & 15) * 4;
        cp_async16(&wb[r*WSTR + c4], g_wtf + r*CH + c4);
    }
    CP_COMMIT();
    CP_WAIT0();
    __syncthreads();

    const int lane = tid & 31, w = tid >> 5;
    const int gID = lane >> 2, tig = lane & 3;
    const int r0 = w*32 + gID;

    float acc[2][8][4];
#pragma unroll
    for (int mt = 0; mt < 2; mt++)
#pragma unroll
        for (int nb = 0; nb < 8; nb++)
#pragma unroll
            for (int j = 0; j < 4; j++) acc[mt][nb][j] = 0.f;

    for (int k = 0; k < KT; k++) {
        const float* wcur = wb + (k & 1) * CH*WSTR;
        if (k < KT-1) {
            const float* wsrc = g_wtf + (k+1)*CH*CH;
            float* wnext = wb + ((k+1) & 1) * CH*WSTR;
            for (int i = tid; i < CH*16; i += CONV_THREADS) {
                int r = i >> 4, c4 = (i & 15) * 4;
                cp_async16(&wnext[r*WSTR + c4], wsrc + r*CH + c4);
            }
            CP_COMMIT();
        }
#pragma unroll
        for (int kk = 0; kk < 8; kk++) {
            const float* xp = xs + (r0 + k)*XSTR + kk*8 + tig;
            uint32_t a0[4], a1[4];
            a0[0] = __float_as_uint(xp[0]);
            a0[1] = __float_as_uint(xp[8*XSTR]);
            a0[2] = __float_as_uint(xp[4]);
            a0[3] = __float_as_uint(xp[8*XSTR + 4]);
            a1[0] = __float_as_uint(xp[16*XSTR]);
            a1[1] = __float_as_uint(xp[24*XSTR]);
            a1[2] = __float_as_uint(xp[16*XSTR + 4]);
            a1[3] = __float_as_uint(xp[24*XSTR + 4]);
            const float* wp = wcur + (kk*8 + tig)*WSTR + gID;
#pragma unroll
            for (int nb = 0; nb < 8; nb++) {
                uint32_t b0 = __float_as_uint(wp[nb*8]);
                uint32_t b1 = __float_as_uint(wp[nb*8 + 4*WSTR]);
                mma_tf32(acc[0][nb], a0, b0, b1);
                mma_tf32(acc[1][nb], a1, b0, b1);
            }
        }
        if (k < KT-1) {
            CP_WAIT0();
            __syncthreads();
        }
    }

    // Epilogue: BN fold + ReLU + residual
#pragma unroll
    for (int mt = 0; mt < 2; mt++) {
#pragma unroll
        for (int nb = 0; nb < 8; nb++) {
            int co = nb*8 + tig*2;
            float2 scl = *(const float2*)&g_scale[co];
            float2 sft = *(const float2*)&g_shift[co];
#pragma unroll
            for (int rr = 0; rr < 2; rr++) {
                int tl = w*32 + mt*16 + gID + rr*8;
                if (tl >= 150) continue;
                int t = tbase + tl;
                long long o = (((long long)nm*TLEN + t)*VJ + v)*CH + co;
                float x0 = fmaxf(acc[mt][nb][rr*2]  *scl.x + sft.x, 0.f);
                float x1 = fmaxf(acc[mt][nb][rr*2+1]*scl.y + sft.y, 0.f);
                float2 hv = *(const float2*)&h[o];
                *(float2*)&out[o] = make_float2(x0 + hv.x, x1 + hv.y);
            }
        }
    }
}

// ============================ launch ============================
extern "C" void kernel_launch(void* const* d_in, const int* in_sizes, int n_in,
                              void* d_out, int out_size) {
    const float* h        = (const float*)d_in[0];
    const float* adj      = (const float*)d_in[1];
    const float* gcn_w    = (const float*)d_in[2];
    const float* gcn_b    = (const float*)d_in[3];
    const float* conv_w   = (const float*)d_in[4];
    const float* conv_b   = (const float*)d_in[5];
    const float* bn_gamma = (const float*)d_in[6];
    const float* bn_beta  = (const float*)d_in[7];
    const float* bn_mean  = (const float*)d_in[8];
    const float* bn_var   = (const float*)d_in[9];
    float* out = (float*)d_out;

    const int gcn_smem  = (112*GSTR_H + 64*GSTR_W + 128*GSTR_HW + 32*GSTR_A + CH + 32) * (int)sizeof(float);
    const int conv_smem = (XROWS*XSTR + 2*CH*WSTR) * (int)sizeof(float);   // 82,560 B
    cudaFuncSetAttribute(gcn_kernel,      cudaFuncAttributeMaxDynamicSharedMemorySize, gcn_smem);
    cudaFuncSetAttribute(conv_mma_kernel, cudaFuncAttributeMaxDynamicSharedMemorySize, conv_smem);

    prep_kernel<<<64, 256>>>(conv_w, conv_b, bn_gamma, bn_beta, bn_mean, bn_var);
    gcn_kernel<<<NSKEL/GCN_S, 256, gcn_smem>>>(h, adj, gcn_w, gcn_b);
    conv_mma_kernel<<<NMB*VJ*2, CONV_THREADS, conv_smem>>>(h, out);
}

// round 5
// speedup vs baseline: 2.1181x; 2.1181x over previous
#include <cuda_runtime.h>
#include <cuda_fp16.h>
#include <cstdint>

// Problem constants
#define NMB 32          // N*M
#define TLEN 300
#define VJ 25
#define CH 64
#define KT 9
#define NSKEL (NMB*TLEN)          // 9600 skeletons

// -------- scratch --------
__device__ __half g_xg[NMB*VJ*TLEN*CH];            // GCN output (nm,v,t,c), fp16
__device__ __align__(16) uint32_t g_w2[KT*CH*36];  // conv W packed [tap][co][p(ci/2)] half2, padded p->36
__device__ float g_scale[CH];                      // BN fold: gamma/sqrt(var+eps)
__device__ float g_shift[CH];                      // (conv_b - mean)*scale + beta

__device__ __forceinline__ float to_tf32(float v) {
    uint32_t u;
    asm("cvt.rna.tf32.f32 %0, %1;" : "=r"(u) : "f"(v));
    return __uint_as_float(u);
}

__device__ __forceinline__ void cp_async16(void* dst_smem, const void* src) {
    uint32_t d = (uint32_t)__cvta_generic_to_shared(dst_smem);
    asm volatile("cp.async.ca.shared.global [%0], [%1], 16;" :: "r"(d), "l"(src));
}
#define CP_COMMIT() asm volatile("cp.async.commit_group;")
#define CP_WAIT0()  asm volatile("cp.async.wait_group 0;")

__device__ __forceinline__ void mma_tf32(float* d, const uint32_t* a, uint32_t b0, uint32_t b1) {
    asm volatile("mma.sync.aligned.m16n8k8.row.col.f32.tf32.tf32.f32 "
        "{%0,%1,%2,%3}, {%4,%5,%6,%7}, {%8,%9}, {%0,%1,%2,%3};"
        : "+f"(d[0]), "+f"(d[1]), "+f"(d[2]), "+f"(d[3])
        : "r"(a[0]), "r"(a[1]), "r"(a[2]), "r"(a[3]), "r"(b0), "r"(b1));
}

__device__ __forceinline__ void mma_f16(float* d, const uint32_t* a, uint32_t b0, uint32_t b1) {
    asm volatile("mma.sync.aligned.m16n8k16.row.col.f32.f16.f16.f32 "
        "{%0,%1,%2,%3}, {%4,%5,%6,%7}, {%8,%9}, {%0,%1,%2,%3};"
        : "+f"(d[0]), "+f"(d[1]), "+f"(d[2]), "+f"(d[3])
        : "r"(a[0]), "r"(a[1]), "r"(a[2]), "r"(a[3]), "r"(b0), "r"(b1));
}

// ============================ prep ============================
__global__ void prep_kernel(const float* __restrict__ conv_w,
                            const float* __restrict__ conv_b,
                            const float* __restrict__ bn_gamma,
                            const float* __restrict__ bn_beta,
                            const float* __restrict__ bn_mean,
                            const float* __restrict__ bn_var) {
    const int gtid = blockIdx.x * blockDim.x + threadIdx.x;
    const int gstride = gridDim.x * blockDim.x;
    if (gtid < CH) {
        float inv = bn_gamma[gtid] * rsqrtf(bn_var[gtid] + 1e-5f);
        g_scale[gtid] = inv;
        g_shift[gtid] = (conv_b[gtid] - bn_mean[gtid]) * inv + bn_beta[gtid];
    }
    // conv_w (co, ci, k) -> g_w2[k][co][p] = half2(w[2p][co], w[2p+1][co]), p<32; pad 32..35 = 0
    for (int i = gtid; i < KT*CH*36; i += gstride) {
        int k   = i / (CH*36);
        int rem = i - k*(CH*36);
        int co  = rem / 36;
        int p   = rem % 36;
        uint32_t val = 0;
        if (p < 32) {
            float w0 = conv_w[(co*CH + 2*p    )*KT + k];
            float w1 = conv_w[(co*CH + 2*p + 1)*KT + k];
            __half2 h2 = __floats2half2_rn(w0, w1);
            val = *(uint32_t*)&h2;
        }
        g_w2[i] = val;
    }
}

// ============================ GCN (tf32 MMA, fp16 output) ============================
#define GSTR_H 68
#define GSTR_W 72
#define GSTR_HW 72
#define GSTR_A 36
#define GCN_S 4

__global__ __launch_bounds__(256, 2)
void gcn_kernel(const float* __restrict__ h,
                const float* __restrict__ adj,
                const float* __restrict__ gcn_w,
                const float* __restrict__ gcn_b) {
    extern __shared__ float sm[];
    float* hs  = sm;                       // 112*68
    float* Ws  = hs  + 112*GSTR_H;         // 64*72
    float* hw  = Ws  + 64*GSTR_W;          // 128*72
    float* Ah  = hw  + 128*GSTR_HW;        // 32*36
    float* gb  = Ah  + 32*GSTR_A;          // 64
    float* nrm = gb  + CH;                 // 25

    const int tid = threadIdx.x;
    const int g0  = blockIdx.x * GCN_S;
    const float* hbase = h + (long long)g0 * VJ * CH;

    if (tid < VJ) {
        float s = 0.f;
        for (int u = 0; u < VJ; u++) s += adj[tid*VJ + u];
        nrm[tid] = rsqrtf(s);
    }
    for (int i = tid; i < 112*16; i += 256) {
        int r = i >> 4, c4 = (i & 15) * 4;
        float4 v = make_float4(0,0,0,0);
        if (r < 100) {
            v = *(const float4*)&hbase[r*CH + c4];
            v.x = to_tf32(v.x); v.y = to_tf32(v.y); v.z = to_tf32(v.z); v.w = to_tf32(v.w);
        }
        *(float4*)&hs[r*GSTR_H + c4] = v;
    }
    for (int i = tid; i < CH*16; i += 256) {
        int r = i >> 4, c4 = (i & 15) * 4;
        float4 v = *(const float4*)&gcn_w[r*CH + c4];
        v.x = to_tf32(v.x); v.y = to_tf32(v.y); v.z = to_tf32(v.z); v.w = to_tf32(v.w);
        *(float4*)&Ws[r*GSTR_W + c4] = v;
    }
    for (int i = tid; i < GCN_S*7*18; i += 256) {
        int j = i / 18, c4 = (i % 18) * 4;
        int s = j / 7, rr = j % 7;
        *(float4*)&hw[(s*32 + 25 + rr)*GSTR_HW + c4] = make_float4(0,0,0,0);
    }
    if (tid < CH) gb[tid] = gcn_b[tid];
    __syncthreads();

    for (int i = tid; i < 32*32; i += 256) {
        int v = i >> 5, u = i & 31;
        Ah[v*GSTR_A + u] = (v < VJ && u < VJ) ? to_tf32(nrm[v]*adj[v*VJ+u]*nrm[u]) : 0.f;
    }
    __syncthreads();

    const int lane = tid & 31, w = tid >> 5;
    const int gID = lane >> 2, tig = lane & 3;

    // GEMM1: hw = hs @ Ws, warps 0-6
    if (w < 7) {
        float acc[8][4];
#pragma unroll
        for (int nb = 0; nb < 8; nb++)
#pragma unroll
            for (int j = 0; j < 4; j++) acc[nb][j] = 0.f;
#pragma unroll
        for (int kk = 0; kk < 8; kk++) {
            const float* xp = hs + (w*16 + gID)*GSTR_H + kk*8 + tig;
            uint32_t a[4];
            a[0] = __float_as_uint(xp[0]);
            a[1] = __float_as_uint(xp[8*GSTR_H]);
            a[2] = __float_as_uint(xp[4]);
            a[3] = __float_as_uint(xp[8*GSTR_H + 4]);
            const float* wp = Ws + (kk*8 + tig)*GSTR_W + gID;
#pragma unroll
            for (int nb = 0; nb < 8; nb++) {
                uint32_t b0 = __float_as_uint(wp[nb*8]);
                uint32_t b1 = __float_as_uint(wp[nb*8 + 4*GSTR_W]);
                mma_tf32(acc[nb], a, b0, b1);
            }
        }
#pragma unroll
        for (int nb = 0; nb < 8; nb++) {
            int c = nb*8 + tig*2;
#pragma unroll
            for (int rr = 0; rr < 2; rr++) {
                int r = w*16 + gID + rr*8;
                if (r < 100) {
                    int s = r / VJ, vv = r - s*VJ;
                    float2 val = make_float2(to_tf32(acc[nb][rr*2]), to_tf32(acc[nb][rr*2+1]));
                    *(float2*)&hw[(s*32 + vv)*GSTR_HW + c] = val;
                }
            }
        }
    }
    __syncthreads();

    // GEMM2: x = Ah @ hw_s; epilogue writes fp16 to g_xg
    {
        const int s = w >> 1, mt = w & 1;
        float acc[8][4];
#pragma unroll
        for (int nb = 0; nb < 8; nb++)
#pragma unroll
            for (int j = 0; j < 4; j++) acc[nb][j] = 0.f;
#pragma unroll
        for (int kk = 0; kk < 4; kk++) {
            const float* ap = Ah + (mt*16 + gID)*GSTR_A + kk*8 + tig;
            uint32_t a[4];
            a[0] = __float_as_uint(ap[0]);
            a[1] = __float_as_uint(ap[8*GSTR_A]);
            a[2] = __float_as_uint(ap[4]);
            a[3] = __float_as_uint(ap[8*GSTR_A + 4]);
            const float* wp = hw + (s*32 + kk*8 + tig)*GSTR_HW + gID;
#pragma unroll
            for (int nb = 0; nb < 8; nb++) {
                uint32_t b0 = __float_as_uint(wp[nb*8]);
                uint32_t b1 = __float_as_uint(wp[nb*8 + 4*GSTR_HW]);
                mma_tf32(acc[nb], a, b0, b1);
            }
        }
        const int g = g0 + s;
        const int nm = g / TLEN, t = g % TLEN;
#pragma unroll
        for (int nb = 0; nb < 8; nb++) {
            int c = nb*8 + tig*2;
            float2 gbv = *(const float2*)&gb[c];
#pragma unroll
            for (int rr = 0; rr < 2; rr++) {
                int vv = mt*16 + gID + rr*8;
                if (vv < VJ) {
                    float x0 = fmaxf(acc[nb][rr*2]   + gbv.x, 0.f);
                    float x1 = fmaxf(acc[nb][rr*2+1] + gbv.y, 0.f);
                    __half2 h2 = __floats2half2_rn(x0, x1);
                    *(__half2*)&g_xg[((nm*VJ + vv)*TLEN + t)*CH + c] = h2;
                }
            }
        }
    }
}

// ============================ Conv (fp16 MMA m16n8k16) ============================
// Block = half a (nm,v) slab (150 t-rows). 160 threads = 5 warps, warp = m32 x n64.
// X fp16 smem stride 72 halves (36 u32); W double-buffered [64 co][36 p] half2.
#define XSTR_H 72          // halves
#define XSTR_U 36          // u32
#define WSTR_U 36          // u32 per co row
#define XROWS 168
#define CONV_THREADS 160

__global__ __launch_bounds__(CONV_THREADS, 3)
void conv_mma_kernel(const float* __restrict__ h, float* __restrict__ out) {
    extern __shared__ __align__(16) char smraw[];
    __half*   xs  = (__half*)smraw;                        // 168*72 halves
    uint32_t* xsu = (uint32_t*)smraw;
    uint32_t* wb  = (uint32_t*)(smraw + XROWS*XSTR_H*2);   // 2 * 64*36 u32

    const int tid  = threadIdx.x;
    const int bid  = blockIdx.x;
    const int slab = bid >> 1;
    const int half = bid & 1;
    const int nm = slab / VJ, v = slab % VJ;
    const int tbase = half * 150;
    const __half* xg = g_xg + (long long)slab * TLEN * CH;

    // X fill: row r <-> t = tbase-4+r ; 8 chunks of 16B per row
    for (int i = tid; i < XROWS*8; i += CONV_THREADS) {
        int r = i >> 3, c8 = (i & 7) * 8;
        int tg = tbase - 4 + r;
        __half* dst = &xs[r*XSTR_H + c8];
        if (r < 158 && tg >= 0 && tg < TLEN)
            cp_async16(dst, xg + tg*CH + c8);
        else
            *(float4*)dst = make_float4(0,0,0,0);
    }
    // W tap 0
    for (int i = tid; i < CH*WSTR_U/4; i += CONV_THREADS)
        cp_async16(&wb[i*4], &g_w2[i*4]);
    CP_COMMIT();
    CP_WAIT0();
    __syncthreads();

    const int lane = tid & 31, w = tid >> 5;
    const int gID = lane >> 2, tig = lane & 3;
    const int r0 = w*32 + gID;

    float acc[2][8][4];
#pragma unroll
    for (int mt = 0; mt < 2; mt++)
#pragma unroll
        for (int nb = 0; nb < 8; nb++)
#pragma unroll
            for (int j = 0; j < 4; j++) acc[mt][nb][j] = 0.f;

    for (int k = 0; k < KT; k++) {
        const uint32_t* wcur = wb + (k & 1) * CH*WSTR_U;
        if (k < KT-1) {
            uint32_t* wnext = wb + ((k+1) & 1) * CH*WSTR_U;
            const uint32_t* wsrc = g_w2 + (k+1)*CH*WSTR_U;
            for (int i = tid; i < CH*WSTR_U/4; i += CONV_THREADS)
                cp_async16(&wnext[i*4], &wsrc[i*4]);
            CP_COMMIT();
        }
#pragma unroll
        for (int kk = 0; kk < 4; kk++) {
            int base = (r0 + k)*XSTR_U + kk*8 + tig;
            uint32_t a0[4], a1[4];
            a0[0] = xsu[base];
            a0[1] = xsu[base + 8*XSTR_U];
            a0[2] = xsu[base + 4];
            a0[3] = xsu[base + 8*XSTR_U + 4];
            a1[0] = xsu[base + 16*XSTR_U];
            a1[1] = xsu[base + 24*XSTR_U];
            a1[2] = xsu[base + 16*XSTR_U + 4];
            a1[3] = xsu[base + 24*XSTR_U + 4];
            const uint32_t* wp = wcur + gID*WSTR_U + kk*8 + tig;
#pragma unroll
            for (int nb = 0; nb < 8; nb++) {
                uint32_t b0 = wp[nb*8*WSTR_U];
                uint32_t b1 = wp[nb*8*WSTR_U + 4];
                mma_f16(acc[0][nb], a0, b0, b1);
                mma_f16(acc[1][nb], a1, b0, b1);
            }
        }
        if (k < KT-1) {
            CP_WAIT0();
            __syncthreads();
        }
    }

    // Epilogue: BN fold + ReLU + residual
#pragma unroll
    for (int mt = 0; mt < 2; mt++) {
#pragma unroll
        for (int nb = 0; nb < 8; nb++) {
            int co = nb*8 + tig*2;
            float2 scl = *(const float2*)&g_scale[co];
            float2 sft = *(const float2*)&g_shift[co];
#pragma unroll
            for (int rr = 0; rr < 2; rr++) {
                int tl = w*32 + mt*16 + gID + rr*8;
                if (tl >= 150) continue;
                int t = tbase + tl;
                long long o = (((long long)nm*TLEN + t)*VJ + v)*CH + co;
                float x0 = fmaxf(acc[mt][nb][rr*2]  *scl.x + sft.x, 0.f);
                float x1 = fmaxf(acc[mt][nb][rr*2+1]*scl.y + sft.y, 0.f);
                float2 hv = *(const float2*)&h[o];
                *(float2*)&out[o] = make_float2(x0 + hv.x, x1 + hv.y);
            }
        }
    }
}

// ============================ launch ============================
extern "C" void kernel_launch(void* const* d_in, const int* in_sizes, int n_in,
                              void* d_out, int out_size) {
    const float* h        = (const float*)d_in[0];
    const float* adj      = (const float*)d_in[1];
    const float* gcn_w    = (const float*)d_in[2];
    const float* gcn_b    = (const float*)d_in[3];
    const float* conv_w   = (const float*)d_in[4];
    const float* conv_b   = (const float*)d_in[5];
    const float* bn_gamma = (const float*)d_in[6];
    const float* bn_beta  = (const float*)d_in[7];
    const float* bn_mean  = (const float*)d_in[8];
    const float* bn_var   = (const float*)d_in[9];
    float* out = (float*)d_out;

    const int gcn_smem  = (112*GSTR_H + 64*GSTR_W + 128*GSTR_HW + 32*GSTR_A + CH + 32) * (int)sizeof(float);
    const int conv_smem = XROWS*XSTR_H*2 + 2*CH*WSTR_U*4;   // 24192 + 18432 = 42624 B
    cudaFuncSetAttribute(gcn_kernel,      cudaFuncAttributeMaxDynamicSharedMemorySize, gcn_smem);
    cudaFuncSetAttribute(conv_mma_kernel, cudaFuncAttributeMaxDynamicSharedMemorySize, conv_smem);

    prep_kernel<<<64, 256>>>(conv_w, conv_b, bn_gamma, bn_beta, bn_mean, bn_var);
    gcn_kernel<<<NSKEL/GCN_S, 256, gcn_smem>>>(h, adj, gcn_w, gcn_b);
    conv_mma_kernel<<<NMB*VJ*2, CONV_THREADS, conv_smem>>>(h, out);
}